// round 9
// baseline (speedup 1.0000x reference)
#include <cuda_runtime.h>

// Problem constants (fixed by the dataset)
#define TT 512
#define BB 32
#define NN 64
#define KK 32
#define SAMP_PER_B (TT * NN)                 // 32768 samples per batch element
#define SLICES 32                            // CTAs per batch along sample axis
#define SAMP_PER_CTA (SAMP_PER_B / SLICES)   // 1024
#define CHUNK 64
#define NCHUNK (SAMP_PER_CTA / CHUNK)        // 16
#define THREADS 128
#define U_BLOCKS 64

// Deterministic scratch (no device allocation allowed)
__device__ float g_part[BB * SLICES * 1024];   // 4 MB, fully overwritten each launch
__device__ float g_berg[BB];
__device__ float g_upart[U_BLOCKS];

// ---- packed f32x2 helpers (Blackwell FFMA2) ----
__device__ __forceinline__ double ffma2(double a, double b, double c) {
    double d;
    asm("fma.rn.f32x2 %0, %1, %2, %3;" : "=d"(d) : "d"(a), "d"(b), "d"(c));
    return d;
}
__device__ __forceinline__ double packdup(float a) {
    double d;
    asm("mov.b64 %0, {%1, %2};" : "=d"(d) : "f"(a), "f"(a));
    return d;
}

// smem layout:
//  A table: 64 rows, stride 40 doubles (320B). Row-group g (8 doubles used)
//           at doubles offset g*10 (80B spacing -> conflict-free consumer loads).
//           Values stored PRE-DUPLICATED: double = (v, v) packed f32x2.
//  B table: 64 rows, stride 36 floats (144B), plain float values (adjacent
//           pairs ARE the packed q-pairs when read as doubles).
//  After the main loop the A region is reused as a 4x1024-float reduce buffer.
#define A_STRIDE_D 40
#define A_BYTES (64 * A_STRIDE_D * 8)   // 20480
#define B_STRIDE_F 36
#define B_BYTES (64 * B_STRIDE_F * 4)   // 9216

// ============================================================================
// Pass 1: per-(batch, slice) partial S accumulation.
// 128 threads. Chunked: generate 64 samples' Chebyshev cos tables, then
// consume as 32x32 += A^T B with 8x8 packed-f32x2 register tiles.
// Warp w consumes samples w*16 + ks*2 + half; cross-half via shfl,
// cross-warp via smem -> ONE 1024-float partial per CTA.
// ============================================================================
__global__ void __launch_bounds__(THREADS, 4)
pass1_kernel(const float* __restrict__ x, const float* __restrict__ L) {
    __shared__ __align__(16) unsigned char smem_raw[A_BYTES + B_BYTES];
    double* sAd = (double*)smem_raw;
    float*  sBf = (float*)(smem_raw + A_BYTES);

    const int slice = blockIdx.x;
    const int b     = blockIdx.y;
    const int tid   = threadIdx.x;

    // --- generator role: warps 0-1 -> dim0 (A), warps 2-3 -> dim1 (B) ---
    const int   gs   = tid & 63;
    const int   gdim = tid >> 6;
    const float invL = 3.14159265358979323846f / __ldg(&L[gdim]);

    // --- consumer role ---
    const int lane = tid & 31;
    const int w    = tid >> 5;
    const int rg   = (lane >> 2) & 3;   // row group: rows rg*8 .. rg*8+7
    const int cg   = lane & 3;          // col group: cols cg*8 .. cg*8+7
    const int half = lane >> 4;         // sample parity within warp

    double acc[8][4];
#pragma unroll
    for (int i = 0; i < 8; i++)
#pragma unroll
        for (int j = 0; j < 4; j++) acc[i][j] = 0.0;

    const int sbase = slice * SAMP_PER_CTA;

    const double* aBase = sAd + (w * 16 + half) * A_STRIDE_D + rg * 10;
    const double* bBase = (const double*)(sBf + (w * 16 + half) * B_STRIDE_F) + cg * 4;

    for (int chunk = 0; chunk < NCHUNK; chunk++) {
        // ---- generate cos tables for 64 samples (Chebyshev recurrence) ----
        {
            const int sidx = sbase + chunk * CHUNK + gs;
            const int t = sidx >> 6;
            const int n = sidx & (NN - 1);
            const float xv = x[((t * BB + b) * NN + n) * 2 + gdim];
            const float cv = __cosf(xv * invL);
            const float c2 = cv + cv;
            float p0 = 1.0f, p1 = cv;
            if (gdim == 0) {
                double* row = sAd + gs * A_STRIDE_D;
#pragma unroll
                for (int g2 = 0; g2 < 4; g2++) {
                    const float w0 = p0, w1 = p1;
                    const float w2 = fmaf(c2, w1, -w0);
                    const float w3 = fmaf(c2, w2, -w1);
                    const float w4 = fmaf(c2, w3, -w2);
                    const float w5 = fmaf(c2, w4, -w3);
                    const float w6 = fmaf(c2, w5, -w4);
                    const float w7 = fmaf(c2, w6, -w5);
                    p0 = fmaf(c2, w7, -w6);
                    p1 = fmaf(c2, p0, -w7);
                    double2* dst = (double2*)(row + g2 * 10);
                    dst[0] = make_double2(packdup(w0), packdup(w1));
                    dst[1] = make_double2(packdup(w2), packdup(w3));
                    dst[2] = make_double2(packdup(w4), packdup(w5));
                    dst[3] = make_double2(packdup(w6), packdup(w7));
                }
            } else {
                float* row = sBf + gs * B_STRIDE_F;
#pragma unroll
                for (int g2 = 0; g2 < 4; g2++) {
                    const float w0 = p0, w1 = p1;
                    const float w2 = fmaf(c2, w1, -w0);
                    const float w3 = fmaf(c2, w2, -w1);
                    const float w4 = fmaf(c2, w3, -w2);
                    const float w5 = fmaf(c2, w4, -w3);
                    const float w6 = fmaf(c2, w5, -w4);
                    const float w7 = fmaf(c2, w6, -w5);
                    p0 = fmaf(c2, w7, -w6);
                    p1 = fmaf(c2, p0, -w7);
                    float4* dst = (float4*)(row + g2 * 8);
                    dst[0] = make_float4(w0, w1, w2, w3);
                    dst[1] = make_float4(w4, w5, w6, w7);
                }
            }
        }
        __syncthreads();

        // ---- consume: 8 k-steps per warp (2 samples each via halves) ----
#pragma unroll
        for (int ks = 0; ks < 8; ks++) {
            const double* ap = aBase + ks * (2 * A_STRIDE_D);
            const double* bp = bBase + ks * (2 * B_STRIDE_F / 2);
            const double2 a01 = *(const double2*)(ap + 0);
            const double2 a23 = *(const double2*)(ap + 2);
            const double2 a45 = *(const double2*)(ap + 4);
            const double2 a67 = *(const double2*)(ap + 6);
            const double2 b01 = *(const double2*)(bp + 0);
            const double2 b23 = *(const double2*)(bp + 2);
            const double aa[8] = {a01.x, a01.y, a23.x, a23.y,
                                  a45.x, a45.y, a67.x, a67.y};
            const double bb[4] = {b01.x, b01.y, b23.x, b23.y};
#pragma unroll
            for (int i = 0; i < 8; i++) {
#pragma unroll
                for (int j = 0; j < 4; j++)
                    acc[i][j] = ffma2(aa[i], bb[j], acc[i][j]);
            }
        }
        __syncthreads();
    }

    // ---- cross-half reduction (deterministic: half0 + half1) ----
#pragma unroll
    for (int i = 0; i < 8; i++)
#pragma unroll
        for (int j = 0; j < 4; j++) {
            const double o = __shfl_xor_sync(0xffffffffu, acc[i][j], 16);
            // packed add of the two f32 halves
            double r;
            asm("add.rn.f32x2 %0, %1, %2;" : "=d"(r) : "d"(acc[i][j]), "d"(o));
            acc[i][j] = r;
        }

    // ---- per-warp partial tiles into smem (reusing the A region) ----
    float* sRed = (float*)smem_raw;   // 4 x 1024 floats = 16KB <= A_BYTES
    if (half == 0) {
        float* dstw = sRed + w * 1024;
#pragma unroll
        for (int i = 0; i < 8; i++) {
            const int p = rg * 8 + i;
#pragma unroll
            for (int j = 0; j < 4; j++) {
                // store packed pair directly: (q, q+1) floats
                *(double*)(dstw + p * KK + cg * 8 + 2 * j) = acc[i][j];
            }
        }
    }
    __syncthreads();

    // ---- CTA reduce across the 4 warp partials, write 1 partial tile ----
    {
        const int ob = tid * 8;
        float4 r0 = make_float4(0.f, 0.f, 0.f, 0.f);
        float4 r1 = r0;
#pragma unroll
        for (int ww = 0; ww < 4; ww++) {
            const float4* src = (const float4*)(sRed + ww * 1024 + ob);
            const float4 va = src[0], vb = src[1];
            r0.x += va.x; r0.y += va.y; r0.z += va.z; r0.w += va.w;
            r1.x += vb.x; r1.y += vb.y; r1.z += vb.z; r1.w += vb.w;
        }
        float4* gdst = (float4*)(g_part + ((size_t)b * SLICES + slice) * 1024 + ob);
        gdst[0] = r0;
        gdst[1] = r1;
    }
}

// ============================================================================
// Mid kernel: blocks 0..31 -> per-batch weighted squared-error over modes;
//             blocks 32..95 -> |u|^2 partial sums. 256 threads each.
// ============================================================================
__global__ void mid_kernel(const float* __restrict__ cd,
                           const float* __restrict__ nf,
                           const float* __restrict__ nw,
                           const float4* __restrict__ u4, int n4) {
    const int tid = threadIdx.x;
    __shared__ float red[256];
    float local = 0.0f;

    if (blockIdx.x < BB) {
        const int b = blockIdx.x;
        float4 s = make_float4(0.f, 0.f, 0.f, 0.f);
        const float* base = g_part + (size_t)b * SLICES * 1024 + tid * 4;
#pragma unroll
        for (int sl = 0; sl < SLICES; sl++) {
            const float4 v = *(const float4*)(base + sl * 1024);
            s.x += v.x; s.y += v.y; s.z += v.z; s.w += v.w;
        }
        const float4 vnf = *(const float4*)(nf + tid * 4);
        const float4 vcd = *(const float4*)(cd + tid * 4);
        const float4 vnw = *(const float4*)(nw + tid * 4);
        const float inv = 1.0f / (float)SAMP_PER_B;
        const float d0 = s.x * inv / vnf.x - vcd.x;
        const float d1 = s.y * inv / vnf.y - vcd.y;
        const float d2 = s.z * inv / vnf.z - vcd.z;
        const float d3 = s.w * inv / vnf.w - vcd.w;
        local = d0 * d0 * vnw.x + d1 * d1 * vnw.y
              + d2 * d2 * vnw.z + d3 * d3 * vnw.w;
        red[tid] = local;
        __syncthreads();
        for (int off = 128; off > 0; off >>= 1) {
            if (tid < off) red[tid] += red[tid + off];
            __syncthreads();
        }
        if (tid == 0) g_berg[b] = red[0];
    } else {
        const int ub = blockIdx.x - BB;
        for (int i = ub * 256 + tid; i < n4; i += U_BLOCKS * 256) {
            const float4 v = u4[i];
            local = fmaf(v.x, v.x, local);
            local = fmaf(v.y, v.y, local);
            local = fmaf(v.z, v.z, local);
            local = fmaf(v.w, v.w, local);
        }
        red[tid] = local;
        __syncthreads();
        for (int off = 128; off > 0; off >>= 1) {
            if (tid < off) red[tid] += red[tid + off];
            __syncthreads();
        }
        if (tid == 0) g_upart[ub] = red[0];
    }
}

// ============================================================================
// Final combine.
// ============================================================================
__global__ void final_kernel(float* __restrict__ out) {
    const int tid = threadIdx.x;   // 64
    const float UC = 1.0e-3f / (2.0f * (float)SAMP_PER_B * (float)BB);
    float v = g_upart[tid] * UC + (tid < BB ? g_berg[tid] : 0.0f);
    __shared__ float red[64];
    red[tid] = v;
    __syncthreads();
    for (int off = 32; off > 0; off >>= 1) {
        if (tid < off) red[tid] += red[tid + off];
        __syncthreads();
    }
    if (tid == 0) out[0] = red[0];
}

// ============================================================================
// Launch
// ============================================================================
extern "C" void kernel_launch(void* const* d_in, const int* in_sizes, int n_in,
                              void* d_out, int out_size) {
    const float* x  = (const float*)d_in[0];
    const float* u  = (const float*)d_in[1];
    const float* L  = (const float*)d_in[2];
    const float* cd = (const float*)d_in[3];
    const float* nf = (const float*)d_in[4];
    const float* nw = (const float*)d_in[5];
    float* out = (float*)d_out;

    const int n_u = in_sizes[1];          // T*B*N*2 = 2,097,152

    dim3 grid1(SLICES, BB);
    pass1_kernel<<<grid1, THREADS>>>(x, L);
    mid_kernel<<<BB + U_BLOCKS, 256>>>(cd, nf, nw, (const float4*)u, n_u / 4);
    final_kernel<<<1, 64>>>(out);
}

// round 11
// speedup vs baseline: 1.8531x; 1.8531x over previous
#include <cuda_runtime.h>
#include <cuda_bf16.h>
#include <cstdint>

// Problem constants (fixed by the dataset)
#define TT 512
#define BB 32
#define NN 64
#define KK 32
#define SAMP_PER_B (TT * NN)                 // 32768 samples per batch element
#define SLICES 32                            // sample-slices per batch
#define SAMP_PER_CTA (SAMP_PER_B / SLICES)   // 1024
#define CHUNK 128
#define NCHUNK (SAMP_PER_CTA / CHUNK)        // 8
#define U_BLOCKS 64

// smem tables: 64 rows x 256B data, padded to 272B stride (17*16B -> ldmatrix
// conflict-free: row i's 16B unit lands in bank-group (17*i+k)%8, distinct
// across 8 consecutive rows).
#define ROW_STRIDE 272
#define TBL_BYTES (64 * ROW_STRIDE)          // 17408
// epilogue reuse: 4 warp regions of 64 rows x 36 floats (144B stride)
#define EPI_WARP_BYTES (64 * 144)            // 9216
#define SMEM_BYTES 37120                     // max(2*17408, 4*9216) + pad

// Deterministic scratch (no device allocation allowed)
__device__ float g_part[BB * SLICES * 1024];
__device__ float g_berg[BB];
__device__ float g_upart[U_BLOCKS];

__device__ __forceinline__ uint32_t smem_u32(const void* p) {
    uint32_t a;
    asm("{ .reg .u64 t; cvta.to.shared.u64 t, %1; cvt.u32.u64 %0, t; }"
        : "=r"(a) : "l"(p));
    return a;
}

#define LDSM_X4(r0, r1, r2, r3, addr) \
    asm volatile("ldmatrix.sync.aligned.m8n8.x4.shared.b16 {%0,%1,%2,%3}, [%4];" \
                 : "=r"(r0), "=r"(r1), "=r"(r2), "=r"(r3) : "r"(addr))

#define MMA16816(d, a, bf) \
    asm volatile("mma.sync.aligned.m16n8k16.row.col.f32.bf16.bf16.f32 " \
                 "{%0,%1,%2,%3}, {%4,%5,%6,%7}, {%8,%9}, {%0,%1,%2,%3};" \
                 : "+f"((d)[0]), "+f"((d)[1]), "+f"((d)[2]), "+f"((d)[3]) \
                 : "r"((a)[0]), "r"((a)[1]), "r"((a)[2]), "r"((a)[3]), \
                   "r"((bf)[0]), "r"((bf)[1]))

// ============================================================================
// Pass 1: warp-level bf16 tensor-core batched GEMM with exact hi/lo split.
//
// CTA = (slice, batch). Per 128-sample chunk:
//   gen:  thread t (dim = t>>6, sample-pair sp = t&63) builds Chebyshev cos
//         tables: rows 0-31 = mode hi (bf16), rows 32-63 = mode lo, packed
//         bf16x2 = two adjacent samples.
//   mma:  warp w consumes samples [32w, 32w+32) as 2 ksteps of k=16:
//         D[64 p'][32 q] += A[64 x 16] * (Bh[16 x 32] and Bl[16 x 32]).
// After 8 chunks: epilogue merges hi/lo rows + 4 warps -> S tile -> g_part.
// ============================================================================
__global__ void __launch_bounds__(128)
pass1_kernel(const float* __restrict__ x, const float* __restrict__ L) {
    __shared__ __align__(16) unsigned char sm[SMEM_BYTES];

    const int tid   = threadIdx.x;
    const int lane  = tid & 31;
    const int w     = tid >> 5;
    const int slice = blockIdx.x;
    const int b     = blockIdx.y;

    const uint32_t base = smem_u32(sm);
    const uint32_t SA = base;                 // dim0 table (A: p modes)
    const uint32_t SB = base + TBL_BYTES;     // dim1 table (B: q modes)

    // --- generator role ---
    const int   gdim = tid >> 6;
    const int   sp   = tid & 63;              // sample pair index (2 samples)
    const float invL = 3.14159265358979323846f / __ldg(&L[gdim]);
    const uint32_t gBase = (gdim ? SB : SA) + 4u * sp;

    // --- ldmatrix lane addressing ---
    const int blk = lane >> 3, within = lane & 7;
    // A blocks: m0(r0-7,k0-7) m1(r8-15,k0-7) m2(r0-7,k8-15) m3(r8-15,k8-15)
    const uint32_t aAddr0 = SA + (uint32_t)(((blk & 1) * 8 + within) * ROW_STRIDE
                                            + (blk >> 1) * 16);
    // B blocks: m0(q0-7,k0-7) m1(q0-7,k8-15) m2(q8-15,k0-7) m3(q8-15,k8-15)
    const uint32_t bAddr0 = SB + (uint32_t)(((blk >> 1) * 8 + within) * ROW_STRIDE
                                            + (blk & 1) * 16);

    float acc[4][4][4];
#pragma unroll
    for (int mt = 0; mt < 4; mt++)
#pragma unroll
        for (int nt = 0; nt < 4; nt++)
#pragma unroll
            for (int r = 0; r < 4; r++) acc[mt][nt][r] = 0.0f;

    for (int chunk = 0; chunk < NCHUNK; chunk++) {
        // ---- generate hi/lo bf16 tables for 128 samples ----
        {
            const int t_idx = slice * 16 + chunk * 2 + (sp >> 5);
            const int n0    = (2 * sp) & 63;
            const float* xp = x + (((size_t)(t_idx * BB + b)) * NN + n0) * 2 + gdim;
            const float ca = __cosf(xp[0] * invL);
            const float cb = __cosf(xp[2] * invL);
            const float t2a = ca + ca, t2b = cb + cb;
            float va0 = 1.0f, vb0 = 1.0f;     // mode m
            float va1 = ca,   vb1 = cb;       // mode m+1
#pragma unroll
            for (int m = 0; m < 32; m++) {
                uint32_t hp;
                asm("cvt.rn.satfinite.bf16x2.f32 %0, %1, %2;"
                    : "=r"(hp) : "f"(vb0), "f"(va0));   // low=va0(sample even)
                const float ha = __uint_as_float(hp << 16);
                const float hb = __uint_as_float(hp & 0xffff0000u);
                uint32_t lp;
                asm("cvt.rn.satfinite.bf16x2.f32 %0, %1, %2;"
                    : "=r"(lp) : "f"(vb0 - hb), "f"(va0 - ha));
                asm volatile("st.shared.b32 [%0], %1;"
                             :: "r"(gBase + (uint32_t)(m * ROW_STRIDE)), "r"(hp)
                             : "memory");
                asm volatile("st.shared.b32 [%0], %1;"
                             :: "r"(gBase + (uint32_t)((m + 32) * ROW_STRIDE)), "r"(lp)
                             : "memory");
                const float na = fmaf(t2a, va1, -va0);
                const float nb = fmaf(t2b, vb1, -vb0);
                va0 = va1; va1 = na;
                vb0 = vb1; vb1 = nb;
            }
        }
        __syncthreads();

        // ---- consume: 2 ksteps of 16 samples per warp ----
#pragma unroll
        for (int j = 0; j < 2; j++) {
            const uint32_t kb = (uint32_t)(w * 64 + j * 32);

            uint32_t A[4][4];
#pragma unroll
            for (int mt = 0; mt < 4; mt++)
                LDSM_X4(A[mt][0], A[mt][1], A[mt][2], A[mt][3],
                        aAddr0 + (uint32_t)(mt * 16 * ROW_STRIDE) + kb);

            uint32_t Bh[4][2], Bl[4][2];
            LDSM_X4(Bh[0][0], Bh[0][1], Bh[1][0], Bh[1][1], bAddr0 + kb);
            LDSM_X4(Bh[2][0], Bh[2][1], Bh[3][0], Bh[3][1],
                    bAddr0 + (uint32_t)(16 * ROW_STRIDE) + kb);
            LDSM_X4(Bl[0][0], Bl[0][1], Bl[1][0], Bl[1][1],
                    bAddr0 + (uint32_t)(32 * ROW_STRIDE) + kb);
            LDSM_X4(Bl[2][0], Bl[2][1], Bl[3][0], Bl[3][1],
                    bAddr0 + (uint32_t)(48 * ROW_STRIDE) + kb);

#pragma unroll
            for (int mt = 0; mt < 4; mt++)
#pragma unroll
                for (int nt = 0; nt < 4; nt++) {
                    MMA16816(acc[mt][nt], A[mt], Bh[nt]);
                    MMA16816(acc[mt][nt], A[mt], Bl[nt]);
                }
        }
        __syncthreads();
    }

    // ---- epilogue: warp tiles -> smem (reuse table region) ----
    {
        float* eb = (float*)(sm + w * EPI_WARP_BYTES);
        const int gID = lane >> 2, tg = lane & 3;
#pragma unroll
        for (int mt = 0; mt < 4; mt++) {
            const int r0 = mt * 16 + gID;
#pragma unroll
            for (int nt = 0; nt < 4; nt++) {
                const int c = nt * 8 + 2 * tg;
                *(float2*)(eb + r0 * 36 + c)       = make_float2(acc[mt][nt][0], acc[mt][nt][1]);
                *(float2*)(eb + (r0 + 8) * 36 + c) = make_float2(acc[mt][nt][2], acc[mt][nt][3]);
            }
        }
    }
    __syncthreads();

    // ---- merge hi/lo rows + 4 warps, write partial S tile ----
    {
        const float* smf = (const float*)sm;
        float* dst = g_part + ((size_t)b * SLICES + slice) * 1024;
#pragma unroll
        for (int jj = 0; jj < 8; jj++) {
            const int idx = tid * 8 + jj;
            const int p = idx >> 5, q = idx & 31;
            float s = 0.0f;
#pragma unroll
            for (int ww = 0; ww < 4; ww++) {
                const float* r = smf + ww * (EPI_WARP_BYTES / 4);
                s += r[p * 36 + q] + r[(p + 32) * 36 + q];
            }
            dst[idx] = s;
        }
    }
}

// ============================================================================
// Mid kernel: blocks 0..31 -> per-batch weighted squared-error over modes;
//             blocks 32..95 -> |u|^2 partial sums. 256 threads each.
// ============================================================================
__global__ void mid_kernel(const float* __restrict__ cd,
                           const float* __restrict__ nf,
                           const float* __restrict__ nw,
                           const float4* __restrict__ u4, int n4) {
    const int tid = threadIdx.x;
    __shared__ float red[256];
    float local = 0.0f;

    if (blockIdx.x < BB) {
        const int b = blockIdx.x;
        float4 s = make_float4(0.f, 0.f, 0.f, 0.f);
        const float* base = g_part + (size_t)b * SLICES * 1024 + tid * 4;
#pragma unroll
        for (int sl = 0; sl < SLICES; sl++) {
            const float4 v = *(const float4*)(base + sl * 1024);
            s.x += v.x; s.y += v.y; s.z += v.z; s.w += v.w;
        }
        const float4 vnf = *(const float4*)(nf + tid * 4);
        const float4 vcd = *(const float4*)(cd + tid * 4);
        const float4 vnw = *(const float4*)(nw + tid * 4);
        const float inv = 1.0f / (float)SAMP_PER_B;
        const float d0 = s.x * inv / vnf.x - vcd.x;
        const float d1 = s.y * inv / vnf.y - vcd.y;
        const float d2 = s.z * inv / vnf.z - vcd.z;
        const float d3 = s.w * inv / vnf.w - vcd.w;
        local = d0 * d0 * vnw.x + d1 * d1 * vnw.y
              + d2 * d2 * vnw.z + d3 * d3 * vnw.w;
        red[tid] = local;
        __syncthreads();
        for (int off = 128; off > 0; off >>= 1) {
            if (tid < off) red[tid] += red[tid + off];
            __syncthreads();
        }
        if (tid == 0) g_berg[b] = red[0];
    } else {
        const int ub = blockIdx.x - BB;
        for (int i = ub * 256 + tid; i < n4; i += U_BLOCKS * 256) {
            const float4 v = u4[i];
            local = fmaf(v.x, v.x, local);
            local = fmaf(v.y, v.y, local);
            local = fmaf(v.z, v.z, local);
            local = fmaf(v.w, v.w, local);
        }
        red[tid] = local;
        __syncthreads();
        for (int off = 128; off > 0; off >>= 1) {
            if (tid < off) red[tid] += red[tid + off];
            __syncthreads();
        }
        if (tid == 0) g_upart[ub] = red[0];
    }
}

// ============================================================================
// Final combine.
// ============================================================================
__global__ void final_kernel(float* __restrict__ out) {
    const int tid = threadIdx.x;   // 64
    const float UC = 1.0e-3f / (2.0f * (float)SAMP_PER_B * (float)BB);
    float v = g_upart[tid] * UC + (tid < BB ? g_berg[tid] : 0.0f);
    __shared__ float red[64];
    red[tid] = v;
    __syncthreads();
    for (int off = 32; off > 0; off >>= 1) {
        if (tid < off) red[tid] += red[tid + off];
        __syncthreads();
    }
    if (tid == 0) out[0] = red[0];
}

// ============================================================================
// Launch
// ============================================================================
extern "C" void kernel_launch(void* const* d_in, const int* in_sizes, int n_in,
                              void* d_out, int out_size) {
    const float* x  = (const float*)d_in[0];
    const float* u  = (const float*)d_in[1];
    const float* L  = (const float*)d_in[2];
    const float* cd = (const float*)d_in[3];
    const float* nf = (const float*)d_in[4];
    const float* nw = (const float*)d_in[5];
    float* out = (float*)d_out;

    const int n_u = in_sizes[1];          // T*B*N*2 = 2,097,152

    dim3 grid1(SLICES, BB);               // 32 x 32 = 1024 CTAs
    pass1_kernel<<<grid1, 128>>>(x, L);
    mid_kernel<<<BB + U_BLOCKS, 256>>>(cd, nf, nw, (const float4*)u, n_u / 4);
    final_kernel<<<1, 64>>>(out);
}

// round 12
// speedup vs baseline: 2.0677x; 1.1158x over previous
#include <cuda_runtime.h>
#include <cuda_bf16.h>
#include <cstdint>

// Problem constants (fixed by the dataset)
#define TT 512
#define BB 32
#define NN 64
#define KK 32
#define SAMP_PER_B (TT * NN)                 // 32768 samples per batch element
#define SLICES 32                            // sample-slices per batch
#define SAMP_PER_CTA (SAMP_PER_B / SLICES)   // 1024
#define CHUNK 128
#define NCHUNK (SAMP_PER_CTA / CHUNK)        // 8
#define U_BLOCKS 64

// smem tables: 64 rows (32 hi modes + 32 lo modes) x 256B data, padded to
// 272B stride (17*16B -> ldmatrix conflict-free).
#define ROW_STRIDE 272
#define TBL_BYTES (64 * ROW_STRIDE)          // 17408
// epilogue reuse: 4 warp regions of 32 rows x 36 floats (144B stride)
#define EPI_WARP_F 1152                      // floats per warp region (4608 B)
#define SMEM_BYTES (2 * TBL_BYTES)           // 34816

// Deterministic scratch (no device allocation allowed)
__device__ float g_part[BB * SLICES * 1024];
__device__ float g_berg[BB];
__device__ float g_upart[U_BLOCKS];

__device__ __forceinline__ uint32_t smem_u32(const void* p) {
    uint32_t a;
    asm("{ .reg .u64 t; cvta.to.shared.u64 t, %1; cvt.u32.u64 %0, t; }"
        : "=r"(a) : "l"(p));
    return a;
}

#define LDSM_X4(r0, r1, r2, r3, addr) \
    asm volatile("ldmatrix.sync.aligned.m8n8.x4.shared.b16 {%0,%1,%2,%3}, [%4];" \
                 : "=r"(r0), "=r"(r1), "=r"(r2), "=r"(r3) : "r"(addr))

#define MMA16816(d, a, bf) \
    asm volatile("mma.sync.aligned.m16n8k16.row.col.f32.bf16.bf16.f32 " \
                 "{%0,%1,%2,%3}, {%4,%5,%6,%7}, {%8,%9}, {%0,%1,%2,%3};" \
                 : "+f"((d)[0]), "+f"((d)[1]), "+f"((d)[2]), "+f"((d)[3]) \
                 : "r"((a)[0]), "r"((a)[1]), "r"((a)[2]), "r"((a)[3]), \
                   "r"((bf)[0]), "r"((bf)[1]))

#define STS32(addr, v) \
    asm volatile("st.shared.b32 [%0], %1;" :: "r"(addr), "r"(v) : "memory")

// ============================================================================
// Pass 1: warp-level bf16 tensor-core batched GEMM, exact-ish hi/lo split.
// CTA = (slice, batch). Single 32x32 f32 acc per warp:
//   D += Ah*Bh + Ah*Bl + Al*Bh      (Al*Bl dropped: <= 2^-18 rel per term)
// Gen: even/odd Chebyshev chains (cos 2theta recurrence) -> 16-step chains.
// ============================================================================
__global__ void __launch_bounds__(128, 5)
pass1_kernel(const float* __restrict__ x, const float* __restrict__ L) {
    __shared__ __align__(16) unsigned char sm[SMEM_BYTES];

    const int tid   = threadIdx.x;
    const int lane  = tid & 31;
    const int w     = tid >> 5;
    const int slice = blockIdx.x;
    const int b     = blockIdx.y;

    const uint32_t base = smem_u32(sm);
    const uint32_t SA = base;                 // dim0 table (A: p modes)
    const uint32_t SB = base + TBL_BYTES;     // dim1 table (B: q modes)

    // --- generator role: thread t -> dim = t>>6, sample-pair sp = t&63 ---
    const int   gdim = tid >> 6;
    const int   sp   = tid & 63;
    const float invL = 3.14159265358979323846f / __ldg(&L[gdim]);
    const uint32_t gBase = (gdim ? SB : SA) + 4u * sp;

    // --- ldmatrix lane addressing (proven mapping from R10) ---
    const int blk = lane >> 3, within = lane & 7;
    const uint32_t aAddr0 = SA + (uint32_t)(((blk & 1) * 8 + within) * ROW_STRIDE
                                            + (blk >> 1) * 16);
    const uint32_t bAddr0 = SB + (uint32_t)(((blk >> 1) * 8 + within) * ROW_STRIDE
                                            + (blk & 1) * 16);

    float acc[2][4][4];
#pragma unroll
    for (int mt = 0; mt < 2; mt++)
#pragma unroll
        for (int nt = 0; nt < 4; nt++)
#pragma unroll
            for (int r = 0; r < 4; r++) acc[mt][nt][r] = 0.0f;

    for (int chunk = 0; chunk < NCHUNK; chunk++) {
        // ---- generate hi/lo bf16 tables for 128 samples ----
        {
            const int t_idx = slice * 16 + chunk * 2 + (sp >> 5);
            const int n0    = (2 * sp) & 63;
            const float* xp = x + (((size_t)(t_idx * BB + b)) * NN + n0) * 2 + gdim;
            const float c1a = __cosf(xp[0] * invL);
            const float c1b = __cosf(xp[2] * invL);
            const float c2a = fmaf(c1a + c1a, c1a, -1.0f);   // cos 2theta
            const float c2b = fmaf(c1b + c1b, c1b, -1.0f);
            const float t2a = c2a + c2a, t2b = c2b + c2b;
            // even chain: modes 0,2,4,... ; odd chain: modes 1,3,5,...
            float ea0 = 1.0f, ea1 = c2a;
            float eb0 = 1.0f, eb1 = c2b;
            float oa0 = c1a,  oa1 = fmaf(t2a, c1a, -c1a);
            float ob0 = c1b,  ob1 = fmaf(t2b, c1b, -c1b);
#pragma unroll
            for (int i = 0; i < 16; i++) {
                uint32_t hp, lp;
                // even mode 2i
                asm("cvt.rn.satfinite.bf16x2.f32 %0, %1, %2;"
                    : "=r"(hp) : "f"(eb0), "f"(ea0));
                {
                    const float ha = __uint_as_float(hp << 16);
                    const float hb = __uint_as_float(hp & 0xffff0000u);
                    asm("cvt.rn.satfinite.bf16x2.f32 %0, %1, %2;"
                        : "=r"(lp) : "f"(eb0 - hb), "f"(ea0 - ha));
                }
                STS32(gBase + (uint32_t)((2 * i) * ROW_STRIDE), hp);
                STS32(gBase + (uint32_t)((2 * i + 32) * ROW_STRIDE), lp);
                // odd mode 2i+1
                asm("cvt.rn.satfinite.bf16x2.f32 %0, %1, %2;"
                    : "=r"(hp) : "f"(ob0), "f"(oa0));
                {
                    const float ha = __uint_as_float(hp << 16);
                    const float hb = __uint_as_float(hp & 0xffff0000u);
                    asm("cvt.rn.satfinite.bf16x2.f32 %0, %1, %2;"
                        : "=r"(lp) : "f"(ob0 - hb), "f"(oa0 - ha));
                }
                STS32(gBase + (uint32_t)((2 * i + 1) * ROW_STRIDE), hp);
                STS32(gBase + (uint32_t)((2 * i + 33) * ROW_STRIDE), lp);
                // advance all four chains
                const float na = fmaf(t2a, ea1, -ea0); ea0 = ea1; ea1 = na;
                const float nb = fmaf(t2b, eb1, -eb0); eb0 = eb1; eb1 = nb;
                const float ma = fmaf(t2a, oa1, -oa0); oa0 = oa1; oa1 = ma;
                const float mb = fmaf(t2b, ob1, -ob0); ob0 = ob1; ob1 = mb;
            }
        }
        __syncthreads();

        // ---- consume: 2 ksteps of 16 samples per warp ----
#pragma unroll
        for (int j = 0; j < 2; j++) {
            const uint32_t kb = (uint32_t)(w * 64 + j * 32);

            uint32_t Ah[2][4], Al[2][4], Bh[4][2], Bl[4][2];
            LDSM_X4(Ah[0][0], Ah[0][1], Ah[0][2], Ah[0][3], aAddr0 + kb);
            LDSM_X4(Ah[1][0], Ah[1][1], Ah[1][2], Ah[1][3],
                    aAddr0 + (uint32_t)(16 * ROW_STRIDE) + kb);
            LDSM_X4(Al[0][0], Al[0][1], Al[0][2], Al[0][3],
                    aAddr0 + (uint32_t)(32 * ROW_STRIDE) + kb);
            LDSM_X4(Al[1][0], Al[1][1], Al[1][2], Al[1][3],
                    aAddr0 + (uint32_t)(48 * ROW_STRIDE) + kb);
            LDSM_X4(Bh[0][0], Bh[0][1], Bh[1][0], Bh[1][1], bAddr0 + kb);
            LDSM_X4(Bh[2][0], Bh[2][1], Bh[3][0], Bh[3][1],
                    bAddr0 + (uint32_t)(16 * ROW_STRIDE) + kb);
            LDSM_X4(Bl[0][0], Bl[0][1], Bl[1][0], Bl[1][1],
                    bAddr0 + (uint32_t)(32 * ROW_STRIDE) + kb);
            LDSM_X4(Bl[2][0], Bl[2][1], Bl[3][0], Bl[3][1],
                    bAddr0 + (uint32_t)(48 * ROW_STRIDE) + kb);

            // three product passes; 8 independent accs between same-acc reuse
#pragma unroll
            for (int mt = 0; mt < 2; mt++)
#pragma unroll
                for (int nt = 0; nt < 4; nt++)
                    MMA16816(acc[mt][nt], Ah[mt], Bh[nt]);
#pragma unroll
            for (int mt = 0; mt < 2; mt++)
#pragma unroll
                for (int nt = 0; nt < 4; nt++)
                    MMA16816(acc[mt][nt], Ah[mt], Bl[nt]);
#pragma unroll
            for (int mt = 0; mt < 2; mt++)
#pragma unroll
                for (int nt = 0; nt < 4; nt++)
                    MMA16816(acc[mt][nt], Al[mt], Bh[nt]);
        }
        __syncthreads();
    }

    // ---- epilogue: warp 32x32 tiles -> smem (reuse table region) ----
    {
        float* eb = (float*)sm + w * EPI_WARP_F;
        const int gID = lane >> 2, tg = lane & 3;
#pragma unroll
        for (int mt = 0; mt < 2; mt++) {
            const int r0 = mt * 16 + gID;
#pragma unroll
            for (int nt = 0; nt < 4; nt++) {
                const int c = nt * 8 + 2 * tg;
                *(float2*)(eb + r0 * 36 + c)       = make_float2(acc[mt][nt][0], acc[mt][nt][1]);
                *(float2*)(eb + (r0 + 8) * 36 + c) = make_float2(acc[mt][nt][2], acc[mt][nt][3]);
            }
        }
    }
    __syncthreads();

    // ---- sum 4 warp tiles, write partial S tile (vectorized) ----
    {
        const float* smf = (const float*)sm;
        const int p  = tid >> 2;
        const int q0 = (tid & 3) * 8;
        float4 s0 = make_float4(0.f, 0.f, 0.f, 0.f);
        float4 s1 = s0;
#pragma unroll
        for (int ww = 0; ww < 4; ww++) {
            const float4* r = (const float4*)(smf + ww * EPI_WARP_F + p * 36 + q0);
            const float4 v0 = r[0], v1 = r[1];
            s0.x += v0.x; s0.y += v0.y; s0.z += v0.z; s0.w += v0.w;
            s1.x += v1.x; s1.y += v1.y; s1.z += v1.z; s1.w += v1.w;
        }
        float4* dst = (float4*)(g_part + ((size_t)b * SLICES + slice) * 1024
                                + p * 32 + q0);
        dst[0] = s0;
        dst[1] = s1;
    }
}

// ============================================================================
// Mid kernel: blocks 0..31 -> per-batch weighted squared-error over modes;
//             blocks 32..95 -> |u|^2 partial sums. 256 threads each.
// ============================================================================
__global__ void mid_kernel(const float* __restrict__ cd,
                           const float* __restrict__ nf,
                           const float* __restrict__ nw,
                           const float4* __restrict__ u4, int n4) {
    const int tid = threadIdx.x;
    __shared__ float red[256];
    float local = 0.0f;

    if (blockIdx.x < BB) {
        const int b = blockIdx.x;
        float4 s = make_float4(0.f, 0.f, 0.f, 0.f);
        const float* base = g_part + (size_t)b * SLICES * 1024 + tid * 4;
#pragma unroll
        for (int sl = 0; sl < SLICES; sl++) {
            const float4 v = *(const float4*)(base + sl * 1024);
            s.x += v.x; s.y += v.y; s.z += v.z; s.w += v.w;
        }
        const float4 vnf = *(const float4*)(nf + tid * 4);
        const float4 vcd = *(const float4*)(cd + tid * 4);
        const float4 vnw = *(const float4*)(nw + tid * 4);
        const float inv = 1.0f / (float)SAMP_PER_B;
        const float d0 = s.x * inv / vnf.x - vcd.x;
        const float d1 = s.y * inv / vnf.y - vcd.y;
        const float d2 = s.z * inv / vnf.z - vcd.z;
        const float d3 = s.w * inv / vnf.w - vcd.w;
        local = d0 * d0 * vnw.x + d1 * d1 * vnw.y
              + d2 * d2 * vnw.z + d3 * d3 * vnw.w;
        red[tid] = local;
        __syncthreads();
        for (int off = 128; off > 0; off >>= 1) {
            if (tid < off) red[tid] += red[tid + off];
            __syncthreads();
        }
        if (tid == 0) g_berg[b] = red[0];
    } else {
        const int ub = blockIdx.x - BB;
        for (int i = ub * 256 + tid; i < n4; i += U_BLOCKS * 256) {
            const float4 v = u4[i];
            local = fmaf(v.x, v.x, local);
            local = fmaf(v.y, v.y, local);
            local = fmaf(v.z, v.z, local);
            local = fmaf(v.w, v.w, local);
        }
        red[tid] = local;
        __syncthreads();
        for (int off = 128; off > 0; off >>= 1) {
            if (tid < off) red[tid] += red[tid + off];
            __syncthreads();
        }
        if (tid == 0) g_upart[ub] = red[0];
    }
}

// ============================================================================
// Final combine.
// ============================================================================
__global__ void final_kernel(float* __restrict__ out) {
    const int tid = threadIdx.x;   // 64
    const float UC = 1.0e-3f / (2.0f * (float)SAMP_PER_B * (float)BB);
    float v = g_upart[tid] * UC + (tid < BB ? g_berg[tid] : 0.0f);
    __shared__ float red[64];
    red[tid] = v;
    __syncthreads();
    for (int off = 32; off > 0; off >>= 1) {
        if (tid < off) red[tid] += red[tid + off];
        __syncthreads();
    }
    if (tid == 0) out[0] = red[0];
}

// ============================================================================
// Launch
// ============================================================================
extern "C" void kernel_launch(void* const* d_in, const int* in_sizes, int n_in,
                              void* d_out, int out_size) {
    const float* x  = (const float*)d_in[0];
    const float* u  = (const float*)d_in[1];
    const float* L  = (const float*)d_in[2];
    const float* cd = (const float*)d_in[3];
    const float* nf = (const float*)d_in[4];
    const float* nw = (const float*)d_in[5];
    float* out = (float*)d_out;

    const int n_u = in_sizes[1];          // T*B*N*2 = 2,097,152

    dim3 grid1(SLICES, BB);               // 32 x 32 = 1024 CTAs
    pass1_kernel<<<grid1, 128>>>(x, L);
    mid_kernel<<<BB + U_BLOCKS, 256>>>(cd, nf, nw, (const float4*)u, n_u / 4);
    final_kernel<<<1, 64>>>(out);
}

// round 13
// speedup vs baseline: 3.2008x; 1.5480x over previous
#include <cuda_runtime.h>
#include <cuda_fp16.h>
#include <cstdint>

// Problem constants (fixed by the dataset)
#define TT 512
#define BB 32
#define NN 64
#define KK 32
#define SAMP_PER_B (TT * NN)                 // 32768 samples per batch element
#define SLICES 32                            // sample-slices per batch
#define SAMP_PER_CTA (SAMP_PER_B / SLICES)   // 1024
#define CHUNK 128
#define NCHUNK (SAMP_PER_CTA / CHUNK)        // 8
#define U_BLOCKS 64

// smem tables: 32 rows (modes) x 256B (128 samples x fp16), padded to 272B
// stride (17*16B -> ldmatrix conflict-free).
#define ROW_STRIDE 272
#define TBL_BYTES (32 * ROW_STRIDE)          // 8704
// epilogue reuse: 4 warp regions of 32 rows x 36 floats
#define EPI_WARP_F 1152                      // 4608 B per warp region
#define SMEM_BYTES 18560                     // max(2*8704, 4*4608) + pad

// Deterministic scratch (no device allocation allowed)
__device__ float g_part[BB * SLICES * 1024];
__device__ float g_berg[BB];
__device__ float g_upart[U_BLOCKS];

__device__ __forceinline__ uint32_t smem_u32(const void* p) {
    uint32_t a;
    asm("{ .reg .u64 t; cvta.to.shared.u64 t, %1; cvt.u32.u64 %0, t; }"
        : "=r"(a) : "l"(p));
    return a;
}

#define LDSM_X4(r0, r1, r2, r3, addr) \
    asm volatile("ldmatrix.sync.aligned.m8n8.x4.shared.b16 {%0,%1,%2,%3}, [%4];" \
                 : "=r"(r0), "=r"(r1), "=r"(r2), "=r"(r3) : "r"(addr))

#define MMA16816F16(d, a, bf) \
    asm volatile("mma.sync.aligned.m16n8k16.row.col.f32.f16.f16.f32 " \
                 "{%0,%1,%2,%3}, {%4,%5,%6,%7}, {%8,%9}, {%0,%1,%2,%3};" \
                 : "+f"((d)[0]), "+f"((d)[1]), "+f"((d)[2]), "+f"((d)[3]) \
                 : "r"((a)[0]), "r"((a)[1]), "r"((a)[2]), "r"((a)[3]), \
                   "r"((bf)[0]), "r"((bf)[1]))

#define STS32(addr, v) \
    asm volatile("st.shared.b32 [%0], %1;" :: "r"(addr), "r"(v) : "memory")

// ============================================================================
// Pass 1: warp-level fp16 tensor-core batched GEMM (no hi/lo split: fp16's
// 10 mantissa bits give ~2e-5 loss rel-err, 50x under the 1e-3 gate).
// CTA = (slice, batch), 4 warps, 32x32 f32 acc per warp.
// Gen: even/odd Chebyshev chains (cos 2theta recurrence), fp16x2 pack of
// two adjacent samples per mode row.
// ============================================================================
__global__ void __launch_bounds__(128, 6)
pass1_kernel(const float* __restrict__ x, const float* __restrict__ L) {
    __shared__ __align__(16) unsigned char sm[SMEM_BYTES];

    const int tid   = threadIdx.x;
    const int lane  = tid & 31;
    const int w     = tid >> 5;
    const int slice = blockIdx.x;
    const int b     = blockIdx.y;

    const uint32_t base = smem_u32(sm);
    const uint32_t SA = base;                 // dim0 table (A: p modes)
    const uint32_t SB = base + TBL_BYTES;     // dim1 table (B: q modes)

    // --- generator role: thread t -> dim = t>>6, sample-pair sp = t&63 ---
    const int   gdim = tid >> 6;
    const int   sp   = tid & 63;
    const float invL = 3.14159265358979323846f / __ldg(&L[gdim]);
    const uint32_t gBase = (gdim ? SB : SA) + 4u * sp;

    // --- ldmatrix lane addressing (proven mapping) ---
    const int blk = lane >> 3, within = lane & 7;
    const uint32_t aAddr0 = SA + (uint32_t)(((blk & 1) * 8 + within) * ROW_STRIDE
                                            + (blk >> 1) * 16);
    const uint32_t bAddr0 = SB + (uint32_t)(((blk >> 1) * 8 + within) * ROW_STRIDE
                                            + (blk & 1) * 16);

    float acc[2][4][4];
#pragma unroll
    for (int mt = 0; mt < 2; mt++)
#pragma unroll
        for (int nt = 0; nt < 4; nt++)
#pragma unroll
            for (int r = 0; r < 4; r++) acc[mt][nt][r] = 0.0f;

    for (int chunk = 0; chunk < NCHUNK; chunk++) {
        // ---- generate fp16 cos tables for 128 samples ----
        {
            const int t_idx = slice * 16 + chunk * 2 + (sp >> 5);
            const int n0    = (2 * sp) & 63;
            const float* xp = x + (((size_t)(t_idx * BB + b)) * NN + n0) * 2 + gdim;
            const float c1a = __cosf(xp[0] * invL);
            const float c1b = __cosf(xp[2] * invL);
            const float c2a = fmaf(c1a + c1a, c1a, -1.0f);   // cos 2theta
            const float c2b = fmaf(c1b + c1b, c1b, -1.0f);
            const float t2a = c2a + c2a, t2b = c2b + c2b;
            // even chain: modes 0,2,4,... ; odd chain: modes 1,3,5,...
            float ea0 = 1.0f, ea1 = c2a;
            float eb0 = 1.0f, eb1 = c2b;
            float oa0 = c1a,  oa1 = fmaf(t2a, c1a, -c1a);
            float ob0 = c1b,  ob1 = fmaf(t2b, c1b, -c1b);
#pragma unroll
            for (int i = 0; i < 16; i++) {
                uint32_t ep, op;
                asm("cvt.rn.f16x2.f32 %0, %1, %2;"
                    : "=r"(ep) : "f"(eb0), "f"(ea0));   // low half = ea0
                asm("cvt.rn.f16x2.f32 %0, %1, %2;"
                    : "=r"(op) : "f"(ob0), "f"(oa0));
                STS32(gBase + (uint32_t)((2 * i) * ROW_STRIDE), ep);
                STS32(gBase + (uint32_t)((2 * i + 1) * ROW_STRIDE), op);
                const float na = fmaf(t2a, ea1, -ea0); ea0 = ea1; ea1 = na;
                const float nb = fmaf(t2b, eb1, -eb0); eb0 = eb1; eb1 = nb;
                const float ma = fmaf(t2a, oa1, -oa0); oa0 = oa1; oa1 = ma;
                const float mb = fmaf(t2b, ob1, -ob0); ob0 = ob1; ob1 = mb;
            }
        }
        __syncthreads();

        // ---- consume: 2 ksteps of 16 samples per warp ----
#pragma unroll
        for (int j = 0; j < 2; j++) {
            const uint32_t kb = (uint32_t)(w * 64 + j * 32);

            uint32_t A[2][4], Bf[4][2];
            LDSM_X4(A[0][0], A[0][1], A[0][2], A[0][3], aAddr0 + kb);
            LDSM_X4(A[1][0], A[1][1], A[1][2], A[1][3],
                    aAddr0 + (uint32_t)(16 * ROW_STRIDE) + kb);
            LDSM_X4(Bf[0][0], Bf[0][1], Bf[1][0], Bf[1][1], bAddr0 + kb);
            LDSM_X4(Bf[2][0], Bf[2][1], Bf[3][0], Bf[3][1],
                    bAddr0 + (uint32_t)(16 * ROW_STRIDE) + kb);

#pragma unroll
            for (int mt = 0; mt < 2; mt++)
#pragma unroll
                for (int nt = 0; nt < 4; nt++)
                    MMA16816F16(acc[mt][nt], A[mt], Bf[nt]);
        }
        __syncthreads();
    }

    // ---- epilogue: warp 32x32 tiles -> smem (reuse table region) ----
    {
        float* eb = (float*)sm + w * EPI_WARP_F;
        const int gID = lane >> 2, tg = lane & 3;
#pragma unroll
        for (int mt = 0; mt < 2; mt++) {
            const int r0 = mt * 16 + gID;
#pragma unroll
            for (int nt = 0; nt < 4; nt++) {
                const int c = nt * 8 + 2 * tg;
                *(float2*)(eb + r0 * 36 + c)       = make_float2(acc[mt][nt][0], acc[mt][nt][1]);
                *(float2*)(eb + (r0 + 8) * 36 + c) = make_float2(acc[mt][nt][2], acc[mt][nt][3]);
            }
        }
    }
    __syncthreads();

    // ---- sum 4 warp tiles, write partial S tile (vectorized) ----
    {
        const float* smf = (const float*)sm;
        const int p  = tid >> 2;
        const int q0 = (tid & 3) * 8;
        float4 s0 = make_float4(0.f, 0.f, 0.f, 0.f);
        float4 s1 = s0;
#pragma unroll
        for (int ww = 0; ww < 4; ww++) {
            const float4* r = (const float4*)(smf + ww * EPI_WARP_F + p * 36 + q0);
            const float4 v0 = r[0], v1 = r[1];
            s0.x += v0.x; s0.y += v0.y; s0.z += v0.z; s0.w += v0.w;
            s1.x += v1.x; s1.y += v1.y; s1.z += v1.z; s1.w += v1.w;
        }
        float4* dst = (float4*)(g_part + ((size_t)b * SLICES + slice) * 1024
                                + p * 32 + q0);
        dst[0] = s0;
        dst[1] = s1;
    }
}

// ============================================================================
// Mid kernel: blocks 0..31 -> per-batch weighted squared-error over modes;
//             blocks 32..95 -> |u|^2 partial sums. 256 threads each.
// ============================================================================
__global__ void mid_kernel(const float* __restrict__ cd,
                           const float* __restrict__ nf,
                           const float* __restrict__ nw,
                           const float4* __restrict__ u4, int n4) {
    const int tid = threadIdx.x;
    __shared__ float red[256];
    float local = 0.0f;

    if (blockIdx.x < BB) {
        const int b = blockIdx.x;
        float4 s = make_float4(0.f, 0.f, 0.f, 0.f);
        const float* base = g_part + (size_t)b * SLICES * 1024 + tid * 4;
#pragma unroll
        for (int sl = 0; sl < SLICES; sl++) {
            const float4 v = *(const float4*)(base + sl * 1024);
            s.x += v.x; s.y += v.y; s.z += v.z; s.w += v.w;
        }
        const float4 vnf = *(const float4*)(nf + tid * 4);
        const float4 vcd = *(const float4*)(cd + tid * 4);
        const float4 vnw = *(const float4*)(nw + tid * 4);
        const float inv = 1.0f / (float)SAMP_PER_B;
        const float d0 = s.x * inv / vnf.x - vcd.x;
        const float d1 = s.y * inv / vnf.y - vcd.y;
        const float d2 = s.z * inv / vnf.z - vcd.z;
        const float d3 = s.w * inv / vnf.w - vcd.w;
        local = d0 * d0 * vnw.x + d1 * d1 * vnw.y
              + d2 * d2 * vnw.z + d3 * d3 * vnw.w;
        red[tid] = local;
        __syncthreads();
        for (int off = 128; off > 0; off >>= 1) {
            if (tid < off) red[tid] += red[tid + off];
            __syncthreads();
        }
        if (tid == 0) g_berg[b] = red[0];
    } else {
        const int ub = blockIdx.x - BB;
        for (int i = ub * 256 + tid; i < n4; i += U_BLOCKS * 256) {
            const float4 v = u4[i];
            local = fmaf(v.x, v.x, local);
            local = fmaf(v.y, v.y, local);
            local = fmaf(v.z, v.z, local);
            local = fmaf(v.w, v.w, local);
        }
        red[tid] = local;
        __syncthreads();
        for (int off = 128; off > 0; off >>= 1) {
            if (tid < off) red[tid] += red[tid + off];
            __syncthreads();
        }
        if (tid == 0) g_upart[ub] = red[0];
    }
}

// ============================================================================
// Final combine.
// ============================================================================
__global__ void final_kernel(float* __restrict__ out) {
    const int tid = threadIdx.x;   // 64
    const float UC = 1.0e-3f / (2.0f * (float)SAMP_PER_B * (float)BB);
    float v = g_upart[tid] * UC + (tid < BB ? g_berg[tid] : 0.0f);
    __shared__ float red[64];
    red[tid] = v;
    __syncthreads();
    for (int off = 32; off > 0; off >>= 1) {
        if (tid < off) red[tid] += red[tid + off];
        __syncthreads();
    }
    if (tid == 0) out[0] = red[0];
}

// ============================================================================
// Launch
// ============================================================================
extern "C" void kernel_launch(void* const* d_in, const int* in_sizes, int n_in,
                              void* d_out, int out_size) {
    const float* x  = (const float*)d_in[0];
    const float* u  = (const float*)d_in[1];
    const float* L  = (const float*)d_in[2];
    const float* cd = (const float*)d_in[3];
    const float* nf = (const float*)d_in[4];
    const float* nw = (const float*)d_in[5];
    float* out = (float*)d_out;

    const int n_u = in_sizes[1];          // T*B*N*2 = 2,097,152

    dim3 grid1(SLICES, BB);               // 32 x 32 = 1024 CTAs
    pass1_kernel<<<grid1, 128>>>(x, L);
    mid_kernel<<<BB + U_BLOCKS, 256>>>(cd, nf, nw, (const float4*)u, n_u / 4);
    final_kernel<<<1, 64>>>(out);
}

// round 14
// speedup vs baseline: 3.2375x; 1.0115x over previous
#include <cuda_runtime.h>
#include <cuda_fp16.h>
#include <cstdint>

// Problem constants (fixed by the dataset)
#define TT 512
#define BB 32
#define NN 64
#define KK 32
#define SAMP_PER_B (TT * NN)                 // 32768 samples per batch element
#define SLICES 16                            // sample-slices per batch
#define SAMP_PER_CTA (SAMP_PER_B / SLICES)   // 2048
#define CHUNK 128
#define NCHUNK (SAMP_PER_CTA / CHUNK)        // 16

// smem tables: 32 rows (modes) x 256B (128 samples x fp16), padded to 272B
// stride (17*16B -> ldmatrix conflict-free). Two (A,B) buffers.
#define ROW_STRIDE 272
#define TBL_BYTES (32 * ROW_STRIDE)          // 8704
#define BUF_BYTES (2 * TBL_BYTES)            // 17408 (A + B tables)
#define SMEM_BYTES (2 * BUF_BYTES)           // 34816 (double buffered)
// epilogue reuse: 4 warp regions of 32 rows x 36 floats
#define EPI_WARP_F 1152                      // 4608 B per warp region

#define NCTA (SLICES * BB)                   // 512

// Deterministic scratch (no device allocation allowed)
__device__ float g_part[BB * SLICES * 1024];   // 2 MB
__device__ float g_berg[BB];
__device__ float g_upart[NCTA];

__device__ __forceinline__ uint32_t smem_u32(const void* p) {
    uint32_t a;
    asm("{ .reg .u64 t; cvta.to.shared.u64 t, %1; cvt.u32.u64 %0, t; }"
        : "=r"(a) : "l"(p));
    return a;
}

#define LDSM_X4(r0, r1, r2, r3, addr) \
    asm volatile("ldmatrix.sync.aligned.m8n8.x4.shared.b16 {%0,%1,%2,%3}, [%4];" \
                 : "=r"(r0), "=r"(r1), "=r"(r2), "=r"(r3) : "r"(addr))

#define MMA16816F16(d, a, bf) \
    asm volatile("mma.sync.aligned.m16n8k16.row.col.f32.f16.f16.f32 " \
                 "{%0,%1,%2,%3}, {%4,%5,%6,%7}, {%8,%9}, {%0,%1,%2,%3};" \
                 : "+f"((d)[0]), "+f"((d)[1]), "+f"((d)[2]), "+f"((d)[3]) \
                 : "r"((a)[0]), "r"((a)[1]), "r"((a)[2]), "r"((a)[3]), \
                   "r"((bf)[0]), "r"((bf)[1]))

#define STS32(addr, v) \
    asm volatile("st.shared.b32 [%0], %1;" :: "r"(addr), "r"(v) : "memory")

// ============================================================================
// Pass 1: warp-level fp16 tensor-core batched GEMM, software-pipelined.
// CTA = (slice, batch), 4 warps, 32x32 f32 acc per warp, double-buffered
// cos tables (gen of chunk c+1 overlaps MMA of chunk c, ONE sync per chunk).
// Also folds a strided |u|^2 partial sum (1024 float4 per CTA) whose LDG
// latency hides under gen(0).
// ============================================================================
__global__ void __launch_bounds__(128, 6)
pass1_kernel(const float* __restrict__ x, const float* __restrict__ L,
             const float4* __restrict__ u4) {
    __shared__ __align__(16) unsigned char sm[SMEM_BYTES];
    __shared__ float ured[128];

    const int tid   = threadIdx.x;
    const int lane  = tid & 31;
    const int w     = tid >> 5;
    const int slice = blockIdx.x;
    const int b     = blockIdx.y;
    const int cta   = b * SLICES + slice;

    // ---- |u|^2 partial: issue LDGs immediately (overlap with gen(0)) ----
    float usum = 0.0f;
    {
        const float4* up = u4 + (size_t)cta * 1024 + tid;
#pragma unroll
        for (int i = 0; i < 8; i++) {
            const float4 v = up[i * 128];
            usum = fmaf(v.x, v.x, usum);
            usum = fmaf(v.y, v.y, usum);
            usum = fmaf(v.z, v.z, usum);
            usum = fmaf(v.w, v.w, usum);
        }
    }

    const uint32_t base = smem_u32(sm);

    // --- generator role: thread t -> dim = t>>6, sample-pair sp = t&63 ---
    const int   gdim = tid >> 6;
    const int   sp   = tid & 63;
    const float invL = 3.14159265358979323846f / __ldg(&L[gdim]);
    // gen destination within a buffer: table gdim, column 4*sp
    const uint32_t gOff = (uint32_t)(gdim * TBL_BYTES + 4 * sp);

    // --- ldmatrix lane addressing (proven mapping), relative to buffer ---
    const int blk = lane >> 3, within = lane & 7;
    const uint32_t aOff0 = (uint32_t)(((blk & 1) * 8 + within) * ROW_STRIDE
                                      + (blk >> 1) * 16);
    const uint32_t bOff0 = (uint32_t)(TBL_BYTES
                                      + ((blk >> 1) * 8 + within) * ROW_STRIDE
                                      + (blk & 1) * 16);

    float acc[2][4][4];
#pragma unroll
    for (int mt = 0; mt < 2; mt++)
#pragma unroll
        for (int nt = 0; nt < 4; nt++)
#pragma unroll
            for (int r = 0; r < 4; r++) acc[mt][nt][r] = 0.0f;

    // ---- generator body (chunk c -> buffer bufsel) ----
    auto gen = [&](int c, uint32_t bufbase) {
        const int t_idx = slice * 32 + c * 2 + (sp >> 5);
        const int n0    = (2 * sp) & 63;
        const float* xp = x + (((size_t)(t_idx * BB + b)) * NN + n0) * 2 + gdim;
        const float c1a = __cosf(xp[0] * invL);
        const float c1b = __cosf(xp[2] * invL);
        const float c2a = fmaf(c1a + c1a, c1a, -1.0f);   // cos 2theta
        const float c2b = fmaf(c1b + c1b, c1b, -1.0f);
        const float t2a = c2a + c2a, t2b = c2b + c2b;
        float ea0 = 1.0f, ea1 = c2a;
        float eb0 = 1.0f, eb1 = c2b;
        float oa0 = c1a,  oa1 = fmaf(t2a, c1a, -c1a);
        float ob0 = c1b,  ob1 = fmaf(t2b, c1b, -c1b);
        const uint32_t gb = bufbase + gOff;
#pragma unroll
        for (int i = 0; i < 16; i++) {
            uint32_t ep, op;
            asm("cvt.rn.f16x2.f32 %0, %1, %2;" : "=r"(ep) : "f"(eb0), "f"(ea0));
            asm("cvt.rn.f16x2.f32 %0, %1, %2;" : "=r"(op) : "f"(ob0), "f"(oa0));
            STS32(gb + (uint32_t)((2 * i) * ROW_STRIDE), ep);
            STS32(gb + (uint32_t)((2 * i + 1) * ROW_STRIDE), op);
            const float na = fmaf(t2a, ea1, -ea0); ea0 = ea1; ea1 = na;
            const float nb = fmaf(t2b, eb1, -eb0); eb0 = eb1; eb1 = nb;
            const float ma = fmaf(t2a, oa1, -oa0); oa0 = oa1; oa1 = ma;
            const float mb = fmaf(t2b, ob1, -ob0); ob0 = ob1; ob1 = mb;
        }
    };

    gen(0, base);
    __syncthreads();

    for (int c = 0; c < NCHUNK; c++) {
        const uint32_t cur = base + (uint32_t)((c & 1) * BUF_BYTES);
        const uint32_t nxt = base + (uint32_t)(((c + 1) & 1) * BUF_BYTES);

        // ---- consume chunk c: 2 ksteps of 16 samples per warp ----
#pragma unroll
        for (int j = 0; j < 2; j++) {
            const uint32_t kb = (uint32_t)(w * 64 + j * 32);
            uint32_t A[2][4], Bf[4][2];
            LDSM_X4(A[0][0], A[0][1], A[0][2], A[0][3], cur + aOff0 + kb);
            LDSM_X4(A[1][0], A[1][1], A[1][2], A[1][3],
                    cur + aOff0 + (uint32_t)(16 * ROW_STRIDE) + kb);
            LDSM_X4(Bf[0][0], Bf[0][1], Bf[1][0], Bf[1][1], cur + bOff0 + kb);
            LDSM_X4(Bf[2][0], Bf[2][1], Bf[3][0], Bf[3][1],
                    cur + bOff0 + (uint32_t)(16 * ROW_STRIDE) + kb);
#pragma unroll
            for (int mt = 0; mt < 2; mt++)
#pragma unroll
                for (int nt = 0; nt < 4; nt++)
                    MMA16816F16(acc[mt][nt], A[mt], Bf[nt]);
        }

        // ---- generate chunk c+1 into the other buffer ----
        if (c + 1 < NCHUNK) gen(c + 1, nxt);
        __syncthreads();
    }

    // ---- epilogue: warp 32x32 tiles -> smem (reuse table region) ----
    {
        float* eb = (float*)sm + w * EPI_WARP_F;
        const int gID = lane >> 2, tg = lane & 3;
#pragma unroll
        for (int mt = 0; mt < 2; mt++) {
            const int r0 = mt * 16 + gID;
#pragma unroll
            for (int nt = 0; nt < 4; nt++) {
                const int c = nt * 8 + 2 * tg;
                *(float2*)(eb + r0 * 36 + c)       = make_float2(acc[mt][nt][0], acc[mt][nt][1]);
                *(float2*)(eb + (r0 + 8) * 36 + c) = make_float2(acc[mt][nt][2], acc[mt][nt][3]);
            }
        }
        ured[tid] = usum;
    }
    __syncthreads();

    // ---- sum 4 warp tiles, write partial S tile (vectorized) ----
    {
        const float* smf = (const float*)sm;
        const int p  = tid >> 2;
        const int q0 = (tid & 3) * 8;
        float4 s0 = make_float4(0.f, 0.f, 0.f, 0.f);
        float4 s1 = s0;
#pragma unroll
        for (int ww = 0; ww < 4; ww++) {
            const float4* r = (const float4*)(smf + ww * EPI_WARP_F + p * 36 + q0);
            const float4 v0 = r[0], v1 = r[1];
            s0.x += v0.x; s0.y += v0.y; s0.z += v0.z; s0.w += v0.w;
            s1.x += v1.x; s1.y += v1.y; s1.z += v1.z; s1.w += v1.w;
        }
        float4* dst = (float4*)(g_part + (size_t)cta * 1024 + p * 32 + q0);
        dst[0] = s0;
        dst[1] = s1;
    }

    // ---- deterministic CTA reduce of usum -> g_upart[cta] ----
    __syncthreads();
    for (int off = 64; off > 0; off >>= 1) {
        if (tid < off) ured[tid] += ured[tid + off];
        __syncthreads();
    }
    if (tid == 0) g_upart[cta] = ured[0];
}

// ============================================================================
// Mid kernel: per-batch weighted squared-error over modes (32 blocks).
// ============================================================================
__global__ void mid_kernel(const float* __restrict__ cd,
                           const float* __restrict__ nf,
                           const float* __restrict__ nw) {
    const int tid = threadIdx.x;   // 256
    const int b   = blockIdx.x;
    __shared__ float red[256];

    float4 s = make_float4(0.f, 0.f, 0.f, 0.f);
    const float* base = g_part + (size_t)b * SLICES * 1024 + tid * 4;
#pragma unroll
    for (int sl = 0; sl < SLICES; sl++) {
        const float4 v = *(const float4*)(base + sl * 1024);
        s.x += v.x; s.y += v.y; s.z += v.z; s.w += v.w;
    }
    const float4 vnf = *(const float4*)(nf + tid * 4);
    const float4 vcd = *(const float4*)(cd + tid * 4);
    const float4 vnw = *(const float4*)(nw + tid * 4);
    const float inv = 1.0f / (float)SAMP_PER_B;
    const float d0 = s.x * inv / vnf.x - vcd.x;
    const float d1 = s.y * inv / vnf.y - vcd.y;
    const float d2 = s.z * inv / vnf.z - vcd.z;
    const float d3 = s.w * inv / vnf.w - vcd.w;
    red[tid] = d0 * d0 * vnw.x + d1 * d1 * vnw.y
             + d2 * d2 * vnw.z + d3 * d3 * vnw.w;
    __syncthreads();
    for (int off = 128; off > 0; off >>= 1) {
        if (tid < off) red[tid] += red[tid + off];
        __syncthreads();
    }
    if (tid == 0) g_berg[b] = red[0];
}

// ============================================================================
// Final combine: 512 u-partials + 32 batch terms.
// ============================================================================
__global__ void final_kernel(float* __restrict__ out) {
    const int tid = threadIdx.x;   // 512
    const float UC = 1.0e-3f / (2.0f * (float)SAMP_PER_B * (float)BB);
    float v = g_upart[tid] * UC + (tid < BB ? g_berg[tid] : 0.0f);
    __shared__ float red[512];
    red[tid] = v;
    __syncthreads();
    for (int off = 256; off > 0; off >>= 1) {
        if (tid < off) red[tid] += red[tid + off];
        __syncthreads();
    }
    if (tid == 0) out[0] = red[0];
}

// ============================================================================
// Launch
// ============================================================================
extern "C" void kernel_launch(void* const* d_in, const int* in_sizes, int n_in,
                              void* d_out, int out_size) {
    const float* x  = (const float*)d_in[0];
    const float* u  = (const float*)d_in[1];
    const float* L  = (const float*)d_in[2];
    const float* cd = (const float*)d_in[3];
    const float* nf = (const float*)d_in[4];
    const float* nw = (const float*)d_in[5];
    float* out = (float*)d_out;

    dim3 grid1(SLICES, BB);               // 16 x 32 = 512 CTAs (one wave)
    pass1_kernel<<<grid1, 128>>>(x, L, (const float4*)u);
    mid_kernel<<<BB, 256>>>(cd, nf, nw);
    final_kernel<<<1, 512>>>(out);
}